// round 6
// baseline (speedup 1.0000x reference)
#include <cuda_runtime.h>

typedef unsigned long long u64;
typedef unsigned int u32;

#define T_STEPS 2048
#define NB 8
#define NH 16
#define BH (NB*NH)
#define KF 32
#define VF 64
#define KS 128
#define VS 64

// ---- packed f32x2 helpers ----
__device__ __forceinline__ u64 pack2(float lo, float hi) {
    u64 r;
    asm("mov.b64 %0, {%1, %2};" : "=l"(r) : "r"(__float_as_uint(lo)), "r"(__float_as_uint(hi)));
    return r;
}
__device__ __forceinline__ void unpack2(u64 a, float& lo, float& hi) {
    u32 l, h;
    asm("mov.b64 {%0, %1}, %2;" : "=r"(l), "=r"(h) : "l"(a));
    lo = __uint_as_float(l); hi = __uint_as_float(h);
}
__device__ __forceinline__ u64 fma2_(u64 a, u64 b, u64 c) {
    u64 d; asm("fma.rn.f32x2 %0, %1, %2, %3;" : "=l"(d) : "l"(a), "l"(b), "l"(c)); return d;
}
__device__ __forceinline__ u64 mul2_(u64 a, u64 b) {
    u64 d; asm("mul.rn.f32x2 %0, %1, %2;" : "=l"(d) : "l"(a), "l"(b)); return d;
}

// smem per-step stage (floats):
// [0,32)    kf : natural (16 row-pairs; thread kgp reads pairs 2kgp,2kgp+1 -> 16B @ 16B*kgp)
// [32,64)   qf : same
// [64,192)  ks : 32 16B-chunks; natural chunk g stored at slot (g>>2) + (g&3)*8
//                -> thread kgp reads chunk c (c=0..3) at slot kgp+8c (contiguous 128B per c)
// [192,320) qs : same swizzle
// [320,384) vf | [384,448) vs | [448,453) scalars {df, ds, g, mf, ms} | pad to 456
#define STEP_F 456
#define NSTAGE 16

__global__ __launch_bounds__(512, 1)
void e90_kernel(const float* __restrict__ k_fast, const float* __restrict__ v_fast,
                const float* __restrict__ q_fast, const float* __restrict__ decay_fast,
                const float* __restrict__ k_slow, const float* __restrict__ v_slow,
                const float* __restrict__ q_slow, const float* __restrict__ decay_slow,
                const float* __restrict__ slow_gate, const float* __restrict__ mix_fast,
                const float* __restrict__ mix_slow, const float* __restrict__ S_fast0,
                const float* __restrict__ S_slow0, float* __restrict__ out)
{
    __shared__ __align__(16) float smem[NSTAGE * STEP_F];

    const int tid = threadIdx.x;
    const int bh  = blockIdx.x;
    const int kgp = tid & 7;    // k-group: 8 groups (16 slow rows / 4 fast rows each)
    const int cg  = tid >> 3;   // value column 0..63

    // ---- loader role: threads 0..116 each cp.async one 16B (or 4B) chunk per step ----
    const float* src = 0;
    int   smoff  = -1;
    long  stride = 0;
    bool  wide   = true;
    {
        int c = tid;
        if (c < 8)        {               src = k_fast + (size_t)bh*KF + c*4;      smoff = c*4;                                 stride = (long)BH*KF; }
        else if (c < 16)  { int g = c-8;  src = q_fast + (size_t)bh*KF + g*4;      smoff = 32  + g*4;                           stride = (long)BH*KF; }
        else if (c < 48)  { int g = c-16; src = k_slow + (size_t)bh*KS + g*4;      smoff = 64  + ((g>>2) + ((g&3)<<3))*4;       stride = (long)BH*KS; }
        else if (c < 80)  { int g = c-48; src = q_slow + (size_t)bh*KS + g*4;      smoff = 192 + ((g>>2) + ((g&3)<<3))*4;       stride = (long)BH*KS; }
        else if (c < 96)  { int g = c-80; src = v_fast + (size_t)bh*VF + g*4;      smoff = 320 + g*4;                           stride = (long)BH*VF; }
        else if (c < 112) { int g = c-96; src = v_slow + (size_t)bh*VS + g*4;      smoff = 384 + g*4;                           stride = (long)BH*VS; }
        else if (c < 117) {
            const float* arrs[5] = {decay_fast, decay_slow, slow_gate, mix_fast, mix_slow};
            src = arrs[c-112] + bh; smoff = 448 + (c-112); stride = (long)BH; wide = false;
        }
    }
    const bool pv = (smoff >= 0);

    u32 smem_base;
    {
        u64 a = __cvta_generic_to_shared(smem);
        smem_base = (u32)a;
    }

    auto issue = [&](int step) {
        if (pv && step < T_STEPS) {
            u32 dst = smem_base + ((u32)((step & (NSTAGE-1)) * STEP_F + smoff)) * 4u;
            if (wide) {
                asm volatile("cp.async.cg.shared.global [%0], [%1], 16;" :: "r"(dst), "l"(src));
            } else {
                asm volatile("cp.async.ca.shared.global [%0], [%1], 4;" :: "r"(dst), "l"(src));
            }
            src += stride;
        }
    };

    // ---- prologue: two 4-step groups (steps 0..7) ----
    #pragma unroll
    for (int p = 0; p < 2; p++) {
        issue(4*p); issue(4*p+1); issue(4*p+2); issue(4*p+3);
        asm volatile("cp.async.commit_group;");
    }

    // ---- initial states ----
    // fast: rows 4kgp..4kgp+3, col cg -> Sf[j] = (row 4kgp+2j, row 4kgp+2j+1)
    // slow: rows 16kgp..16kgp+15, col cg -> Ss[p] = (row 16kgp+2p, +1), p=0..7
    u64 Sf[2], Ss[8];
    {
        const float* p0 = S_fast0 + (size_t)bh*KF*VF + (size_t)(4*kgp)*VF + cg;
        Sf[0] = pack2(p0[0],    p0[VF]);
        Sf[1] = pack2(p0[2*VF], p0[3*VF]);
        const float* p1 = S_slow0 + (size_t)bh*KS*VS + (size_t)(16*kgp)*VS + cg;
        #pragma unroll
        for (int p = 0; p < 8; p++)
            Ss[p] = pack2(p1[(size_t)(2*p)*VS], p1[(size_t)(2*p+1)*VS]);
    }

    // output region: [S_f_final | S_s_final | output]
    float* outO = out + (size_t)BH*(KF*VF + KS*VS) + (size_t)bh*VF + cg;
    const bool writer = (kgp == 0);

    for (int t = 0; t < T_STEPS; t += 4) {
        // steps t..t+3 resident once <=1 newer group pending
        asm volatile("cp.async.wait_group 1;");
        __syncthreads();

        // refill: steps t+8..t+11 (stages (t+8..t+11)&15 — disjoint from t..t+7 window)
        issue(t+8); issue(t+9); issue(t+10); issue(t+11);
        asm volatile("cp.async.commit_group;");

        #pragma unroll
        for (int s = 0; s < 4; s++) {
            const float* cur = smem + ((t + s) & (NSTAGE-1)) * STEP_F;

            float4 sc4 = *(const float4*)(cur + 448);
            float df = sc4.x, ds = sc4.y, g = sc4.z, mf = sc4.w;
            float ms = cur[452];
            float de = 1.0f + g * (ds - 1.0f);          // g*ds + (1-g)

            u64 df2 = pack2(df, df);
            u64 de2 = pack2(de, de);

            float vfv = cur[320 + cg];
            float vsv = g * cur[384 + cg];              // fold gate into slow outer product
            u64 vf2 = pack2(vfv, vfv);
            u64 vs2 = pack2(vsv, vsv);

            // ---- fast state: 2 row-pairs x 1 col ----
            ulonglong2 kf = *(const ulonglong2*)(cur + 4*kgp);
            ulonglong2 qf = *(const ulonglong2*)(cur + 32 + 4*kgp);
            u64 accf;
            Sf[0] = fma2_(df2, Sf[0], mul2_(kf.x, vf2));
            accf  = mul2_(qf.x, Sf[0]);
            Sf[1] = fma2_(df2, Sf[1], mul2_(kf.y, vf2));
            accf  = fma2_(qf.y, Sf[1], accf);

            // ---- slow state: 8 row-pairs x 1 col (swizzled: chunk c at slot kgp+8c) ----
            ulonglong2 k0 = *(const ulonglong2*)(cur + 64  + 4*(kgp));
            ulonglong2 k1 = *(const ulonglong2*)(cur + 64  + 4*(kgp + 8));
            ulonglong2 k2 = *(const ulonglong2*)(cur + 64  + 4*(kgp + 16));
            ulonglong2 k3 = *(const ulonglong2*)(cur + 64  + 4*(kgp + 24));
            ulonglong2 q0 = *(const ulonglong2*)(cur + 192 + 4*(kgp));
            ulonglong2 q1 = *(const ulonglong2*)(cur + 192 + 4*(kgp + 8));
            ulonglong2 q2 = *(const ulonglong2*)(cur + 192 + 4*(kgp + 16));
            ulonglong2 q3 = *(const ulonglong2*)(cur + 192 + 4*(kgp + 24));
            u64 kk[8] = { k0.x, k0.y, k1.x, k1.y, k2.x, k2.y, k3.x, k3.y };
            u64 qq[8] = { q0.x, q0.y, q1.x, q1.y, q2.x, q2.y, q3.x, q3.y };

            u64 accs0, accs1;
            Ss[0] = fma2_(de2, Ss[0], mul2_(kk[0], vs2));
            accs0 = mul2_(qq[0], Ss[0]);
            Ss[1] = fma2_(de2, Ss[1], mul2_(kk[1], vs2));
            accs1 = mul2_(qq[1], Ss[1]);
            #pragma unroll
            for (int p = 2; p < 8; p += 2) {
                Ss[p]   = fma2_(de2, Ss[p],   mul2_(kk[p],   vs2));
                accs0   = fma2_(qq[p],   Ss[p],   accs0);
                Ss[p+1] = fma2_(de2, Ss[p+1], mul2_(kk[p+1], vs2));
                accs1   = fma2_(qq[p+1], Ss[p+1], accs1);
            }

            // ---- epilogue: mix, horizontal sum, 8-lane reduce ----
            float f0, f1, s0, s1, s2, s3;
            unpack2(accf, f0, f1);
            unpack2(accs0, s0, s1);
            unpack2(accs1, s2, s3);
            float o = mf * (f0 + f1) + ms * ((s0 + s1) + (s2 + s3));
            o += __shfl_xor_sync(0xffffffffu, o, 1, 8);
            o += __shfl_xor_sync(0xffffffffu, o, 2, 8);
            o += __shfl_xor_sync(0xffffffffu, o, 4, 8);
            if (writer) *outO = o;
            outO += (size_t)BH * VF;
        }
    }

    // ---- final states ----
    {
        float* oSf = out + (size_t)bh*KF*VF + (size_t)(4*kgp)*VF + cg;
        float a0, a1, a2, a3;
        unpack2(Sf[0], a0, a1);
        unpack2(Sf[1], a2, a3);
        oSf[0]    = a0; oSf[VF]   = a1;
        oSf[2*VF] = a2; oSf[3*VF] = a3;

        float* oSs = out + (size_t)BH*KF*VF + (size_t)bh*KS*VS + (size_t)(16*kgp)*VS + cg;
        #pragma unroll
        for (int p = 0; p < 8; p++) {
            float lo, hi; unpack2(Ss[p], lo, hi);
            oSs[(size_t)(2*p)*VS]   = lo;
            oSs[(size_t)(2*p+1)*VS] = hi;
        }
    }
}

extern "C" void kernel_launch(void* const* d_in, const int* in_sizes, int n_in,
                              void* d_out, int out_size) {
    (void)in_sizes; (void)n_in; (void)out_size;
    e90_kernel<<<BH, 512>>>(
        (const float*)d_in[0],  (const float*)d_in[1],  (const float*)d_in[2],
        (const float*)d_in[3],  (const float*)d_in[4],  (const float*)d_in[5],
        (const float*)d_in[6],  (const float*)d_in[7],  (const float*)d_in[8],
        (const float*)d_in[9],  (const float*)d_in[10], (const float*)d_in[11],
        (const float*)d_in[12], (float*)d_out);
}

// round 8
// speedup vs baseline: 1.6903x; 1.6903x over previous
#include <cuda_runtime.h>

typedef unsigned long long u64;
typedef unsigned int u32;

#define T_STEPS 2048
#define NB 8
#define NH 16
#define BH (NB*NH)
#define KF 32
#define VF 64
#define KS 128
#define VS 64

// ---- packed f32x2 helpers ----
__device__ __forceinline__ u64 pack2(float lo, float hi) {
    u64 r;
    asm("mov.b64 %0, {%1, %2};" : "=l"(r) : "r"(__float_as_uint(lo)), "r"(__float_as_uint(hi)));
    return r;
}
__device__ __forceinline__ void unpack2(u64 a, float& lo, float& hi) {
    u32 l, h;
    asm("mov.b64 {%0, %1}, %2;" : "=r"(l), "=r"(h) : "l"(a));
    lo = __uint_as_float(l); hi = __uint_as_float(h);
}
__device__ __forceinline__ u64 fma2_(u64 a, u64 b, u64 c) {
    u64 d; asm("fma.rn.f32x2 %0, %1, %2, %3;" : "=l"(d) : "l"(a), "l"(b), "l"(c)); return d;
}
__device__ __forceinline__ u64 mul2_(u64 a, u64 b) {
    u64 d; asm("mul.rn.f32x2 %0, %1, %2;" : "=l"(d) : "l"(a), "l"(b)); return d;
}

// ---- mbarrier helpers ----
__device__ __forceinline__ void mbar_init(u32 addr, u32 count) {
    asm volatile("mbarrier.init.shared.b64 [%0], %1;" :: "r"(addr), "r"(count) : "memory");
}
__device__ __forceinline__ void mbar_arrive(u32 addr) {
    asm volatile("mbarrier.arrive.release.cta.shared::cta.b64 _, [%0];" :: "r"(addr) : "memory");
}
// wait until the phase with given parity has completed (acquire)
__device__ __forceinline__ void mbar_wait(u32 addr, u32 parity) {
    asm volatile(
        "{\n\t.reg .pred P;\n\t"
        "WL%=:\n\t"
        "mbarrier.try_wait.parity.acquire.cta.shared::cta.b64 P, [%0], %1, 0x989680;\n\t"
        "@P bra WD%=;\n\t"
        "bra WL%=;\n\t"
        "WD%=:\n\t}"
        :: "r"(addr), "r"(parity) : "memory");
}
__device__ __forceinline__ void cp16(u32 dst, const void* s) {
    asm volatile("cp.async.cg.shared.global [%0], [%1], 16;" :: "r"(dst), "l"(s));
}
__device__ __forceinline__ void cp4(u32 dst, const void* s) {
    asm volatile("cp.async.ca.shared.global [%0], [%1], 4;" :: "r"(dst), "l"(s));
}

// smem per-step stage (floats) — identical layout to the proven R4 kernel:
// [0,32) kf | [32,64) qf | [64,192) ks swizzled: chunk g at 64+(g>>1)*4+(g&1)*64
// [192,320) qs same | [320,384) vf | [384,448) vs | [448,453) scalars | pad 456
#define STEP_F 456
#define RING   16          // 16 steps = 4 mega-stages x 4 steps
#define NMEGA  4

__global__ __launch_bounds__(288, 1)
void e90_kernel(const float* __restrict__ k_fast, const float* __restrict__ v_fast,
                const float* __restrict__ q_fast, const float* __restrict__ decay_fast,
                const float* __restrict__ k_slow, const float* __restrict__ v_slow,
                const float* __restrict__ q_slow, const float* __restrict__ decay_slow,
                const float* __restrict__ slow_gate, const float* __restrict__ mix_fast,
                const float* __restrict__ mix_slow, const float* __restrict__ S_fast0,
                const float* __restrict__ S_slow0, float* __restrict__ out)
{
    __shared__ __align__(16) float ring[RING * STEP_F];
    __shared__ __align__(8)  u64  mbar[2 * NMEGA];   // [0..3] full, [4..7] empty

    const int tid = threadIdx.x;
    const int bh  = blockIdx.x;

    const u32 sb = (u32)__cvta_generic_to_shared(ring);
    const u32 bb = (u32)__cvta_generic_to_shared(mbar);

    if (tid == 0) {
        #pragma unroll
        for (int i = 0; i < NMEGA; i++) {
            mbar_init(bb + i*8, 32);                 // full: 32 producer-lane arrives
            mbar_init(bb + (NMEGA + i)*8, 8);        // empty: 8 consumer-warp arrives
        }
    }
    __syncthreads();   // the ONLY block barrier

    if (tid >= 256) {
        // ================= PRODUCER WARP =================
        const int lane = tid - 256;
        const float* src[4];
        int off[4], strd[4], wid[4];
        #pragma unroll
        for (int r = 0; r < 4; r++) {
            int c = r*32 + lane;
            src[r] = 0; off[r] = -1; strd[r] = 0; wid[r] = 1;
            if (c < 8)        {               src[r] = k_fast + (size_t)bh*KF + c*4;  off[r] = c*4;                        strd[r] = BH*KF; }
            else if (c < 16)  { int g = c-8;  src[r] = q_fast + (size_t)bh*KF + g*4;  off[r] = 32  + g*4;                  strd[r] = BH*KF; }
            else if (c < 48)  { int g = c-16; src[r] = k_slow + (size_t)bh*KS + g*4;  off[r] = 64  + (g>>1)*4 + (g&1)*64;  strd[r] = BH*KS; }
            else if (c < 80)  { int g = c-48; src[r] = q_slow + (size_t)bh*KS + g*4;  off[r] = 192 + (g>>1)*4 + (g&1)*64;  strd[r] = BH*KS; }
            else if (c < 96)  { int g = c-80; src[r] = v_fast + (size_t)bh*VF + g*4;  off[r] = 320 + g*4;                  strd[r] = BH*VF; }
            else if (c < 112) { int g = c-96; src[r] = v_slow + (size_t)bh*VS + g*4;  off[r] = 384 + g*4;                  strd[r] = BH*VS; }
            else if (c < 117) {
                const float* a5[5] = {decay_fast, decay_slow, slow_gate, mix_fast, mix_slow};
                src[r] = a5[c-112] + bh; off[r] = 448 + (c-112); strd[r] = BH; wid[r] = 0;
            }
        }

        int sm = 0; u32 eph = 1;   // fresh empty barriers pass parity-1 wait immediately
        for (int m = 0; m < T_STEPS/4; m++) {
            mbar_wait(bb + (NMEGA + sm)*8, eph);     // wait stage free
            u32 stg = sb + (u32)(sm * 4 * STEP_F) * 4u;
            #pragma unroll
            for (int s = 0; s < 4; s++) {
                u32 stp = stg + (u32)(s * STEP_F) * 4u;
                #pragma unroll
                for (int r = 0; r < 4; r++) {
                    if (off[r] >= 0) {
                        u32 dst = stp + (u32)off[r] * 4u;
                        if (wid[r]) cp16(dst, src[r]); else cp4(dst, src[r]);
                        src[r] += strd[r];
                    }
                }
            }
            // .noinc: consume one of the 32 pre-initialized expected arrivals when
            // this lane's cp.asyncs have all landed (default form is inc+arrive = net 0 -> deadlock)
            asm volatile("cp.async.mbarrier.arrive.noinc.shared.b64 [%0];" :: "r"(bb + sm*8) : "memory");
            if (++sm == NMEGA) { sm = 0; eph ^= 1; }
        }
    } else {
        // ================= 8 CONSUMER WARPS (R4 compute body) =================
        const int kgp = tid & 15;   // k-group (16 groups)
        const int cg  = tid >> 4;   // column-group (16 groups of 4 columns)

        // initial states: fast rows 2kgp,2kgp+1 x cols 4cg..4cg+3 ; slow rows 8kgp..+7
        u64 Sf[4], Ss[4][4];
        {
            const float* p0 = S_fast0 + (size_t)bh*KF*VF + (size_t)(2*kgp)*VF + cg*4;
            float4 re = *(const float4*)p0;
            float4 ro = *(const float4*)(p0 + VF);
            Sf[0] = pack2(re.x, ro.x); Sf[1] = pack2(re.y, ro.y);
            Sf[2] = pack2(re.z, ro.z); Sf[3] = pack2(re.w, ro.w);
            #pragma unroll
            for (int p = 0; p < 4; p++) {
                const float* p1 = S_slow0 + (size_t)bh*KS*VS + (size_t)(8*kgp + 2*p)*VS + cg*4;
                float4 se = *(const float4*)p1;
                float4 so = *(const float4*)(p1 + VS);
                Ss[p][0] = pack2(se.x, so.x); Ss[p][1] = pack2(se.y, so.y);
                Ss[p][2] = pack2(se.z, so.z); Ss[p][3] = pack2(se.w, so.w);
            }
        }

        float* outO = out + (size_t)BH*(KF*VF + KS*VS) + (size_t)bh*VF + cg*4;
        const bool writer = (kgp == 0);
        const bool elect  = ((tid & 31) == 0);

        int sm = 0; u32 cph = 0;
        for (int m = 0; m < T_STEPS/4; m++) {
            mbar_wait(bb + sm*8, cph);               // wait stage full (acquire)
            const float* base = ring + sm * 4 * STEP_F;

            #pragma unroll
            for (int s = 0; s < 4; s++) {
                const float* cur = base + s * STEP_F;

                float4 sc4 = *(const float4*)(cur + 448);
                float df = sc4.x, ds = sc4.y, g = sc4.z, mf = sc4.w;
                float ms = cur[452];
                float de = 1.0f + g * (ds - 1.0f);   // g*ds + (1-g)

                u64 df2 = pack2(df, df);
                u64 de2 = pack2(de, de);

                float4 vf4 = *(const float4*)(cur + 320 + cg*4);
                float4 vs4 = *(const float4*)(cur + 384 + cg*4);
                u64 vf2[4] = { pack2(vf4.x, vf4.x), pack2(vf4.y, vf4.y),
                               pack2(vf4.z, vf4.z), pack2(vf4.w, vf4.w) };
                float w0 = g*vs4.x, w1 = g*vs4.y, w2 = g*vs4.z, w3 = g*vs4.w;
                u64 vs2[4] = { pack2(w0, w0), pack2(w1, w1), pack2(w2, w2), pack2(w3, w3) };

                // fast state (1 row-pair x 4 cols)
                u64 kf = *(const u64*)(cur + 2*kgp);
                u64 qf = *(const u64*)(cur + 32 + 2*kgp);
                u64 accf[4];
                #pragma unroll
                for (int j = 0; j < 4; j++) {
                    Sf[j]   = fma2_(df2, Sf[j], mul2_(kf, vf2[j]));
                    accf[j] = mul2_(qf, Sf[j]);
                }

                // slow state (4 row-pairs x 4 cols)
                ulonglong2 kA = *(const ulonglong2*)(cur + 64  + kgp*4);
                ulonglong2 kB = *(const ulonglong2*)(cur + 128 + kgp*4);
                ulonglong2 qA = *(const ulonglong2*)(cur + 192 + kgp*4);
                ulonglong2 qB = *(const ulonglong2*)(cur + 256 + kgp*4);
                u64 kk[4] = { kA.x, kA.y, kB.x, kB.y };
                u64 qq[4] = { qA.x, qA.y, qB.x, qB.y };
                u64 accs[4];
                #pragma unroll
                for (int j = 0; j < 4; j++) {
                    Ss[0][j] = fma2_(de2, Ss[0][j], mul2_(kk[0], vs2[j]));
                    accs[j]  = mul2_(qq[0], Ss[0][j]);
                }
                #pragma unroll
                for (int p = 1; p < 4; p++) {
                    #pragma unroll
                    for (int j = 0; j < 4; j++) {
                        Ss[p][j] = fma2_(de2, Ss[p][j], mul2_(kk[p], vs2[j]));
                        accs[j]  = fma2_(qq[p], Ss[p][j], accs[j]);
                    }
                }

                // mix + horizontal (row-pair) sum
                u64 mf2 = pack2(mf, mf), ms2 = pack2(ms, ms);
                float o[4];
                #pragma unroll
                for (int j = 0; j < 4; j++) {
                    u64 mm = fma2_(ms2, accs[j], mul2_(mf2, accf[j]));
                    float lo, hi; unpack2(mm, lo, hi);
                    o[j] = lo + hi;
                }
                u64 o01 = pack2(o[0], o[1]);
                u64 o23 = pack2(o[2], o[3]);

                // reduce across 16 k-groups (width-16 shuffle, packed)
                #pragma unroll
                for (int msk = 1; msk < 16; msk <<= 1) {
                    u32 lo0, hi0, lo1, hi1;
                    asm("mov.b64 {%0, %1}, %2;" : "=r"(lo0), "=r"(hi0) : "l"(o01));
                    asm("mov.b64 {%0, %1}, %2;" : "=r"(lo1), "=r"(hi1) : "l"(o23));
                    lo0 = __shfl_xor_sync(0xffffffffu, lo0, msk, 16);
                    hi0 = __shfl_xor_sync(0xffffffffu, hi0, msk, 16);
                    lo1 = __shfl_xor_sync(0xffffffffu, lo1, msk, 16);
                    hi1 = __shfl_xor_sync(0xffffffffu, hi1, msk, 16);
                    u64 p01, p23;
                    asm("mov.b64 %0, {%1, %2};" : "=l"(p01) : "r"(lo0), "r"(hi0));
                    asm("mov.b64 %0, {%1, %2};" : "=l"(p23) : "r"(lo1), "r"(hi1));
                    asm("add.rn.f32x2 %0, %0, %1;" : "+l"(o01) : "l"(p01));
                    asm("add.rn.f32x2 %0, %0, %1;" : "+l"(o23) : "l"(p23));
                }
                if (writer) {
                    float a0, a1, a2, a3;
                    unpack2(o01, a0, a1);
                    unpack2(o23, a2, a3);
                    *(float4*)outO = make_float4(a0, a1, a2, a3);
                }
                outO += (size_t)BH * VF;
            }

            if (elect) mbar_arrive(bb + (NMEGA + sm)*8);   // stage consumed
            if (++sm == NMEGA) { sm = 0; cph ^= 1; }
        }

        // final states
        {
            float* oSf = out + (size_t)bh*KF*VF + (size_t)(2*kgp)*VF + cg*4;
            float e0,o0,e1,o1,e2,o2,e3,o3;
            unpack2(Sf[0], e0, o0); unpack2(Sf[1], e1, o1);
            unpack2(Sf[2], e2, o2); unpack2(Sf[3], e3, o3);
            *(float4*)oSf        = make_float4(e0, e1, e2, e3);
            *(float4*)(oSf + VF) = make_float4(o0, o1, o2, o3);

            #pragma unroll
            for (int p = 0; p < 4; p++) {
                float* oSs = out + (size_t)BH*KF*VF + (size_t)bh*KS*VS + (size_t)(8*kgp + 2*p)*VS + cg*4;
                float se0,so0,se1,so1,se2,so2,se3,so3;
                unpack2(Ss[p][0], se0, so0); unpack2(Ss[p][1], se1, so1);
                unpack2(Ss[p][2], se2, so2); unpack2(Ss[p][3], se3, so3);
                *(float4*)oSs        = make_float4(se0, se1, se2, se3);
                *(float4*)(oSs + VS) = make_float4(so0, so1, so2, so3);
            }
        }
    }
}

extern "C" void kernel_launch(void* const* d_in, const int* in_sizes, int n_in,
                              void* d_out, int out_size) {
    (void)in_sizes; (void)n_in; (void)out_size;
    e90_kernel<<<BH, 288>>>(
        (const float*)d_in[0],  (const float*)d_in[1],  (const float*)d_in[2],
        (const float*)d_in[3],  (const float*)d_in[4],  (const float*)d_in[5],
        (const float*)d_in[6],  (const float*)d_in[7],  (const float*)d_in[8],
        (const float*)d_in[9],  (const float*)d_in[10], (const float*)d_in[11],
        (const float*)d_in[12], (float*)d_out);
}

// round 9
// speedup vs baseline: 1.8193x; 1.0763x over previous
#include <cuda_runtime.h>

typedef unsigned long long u64;
typedef unsigned int u32;

#define T_STEPS 2048
#define NB 8
#define NH 16
#define BH (NB*NH)
#define KF 32
#define VF 64
#define KS 128
#define VS 64

// ---- packed f32x2 helpers ----
__device__ __forceinline__ u64 pack2(float lo, float hi) {
    u64 r;
    asm("mov.b64 %0, {%1, %2};" : "=l"(r) : "r"(__float_as_uint(lo)), "r"(__float_as_uint(hi)));
    return r;
}
__device__ __forceinline__ void unpack2(u64 a, float& lo, float& hi) {
    u32 l, h;
    asm("mov.b64 {%0, %1}, %2;" : "=r"(l), "=r"(h) : "l"(a));
    lo = __uint_as_float(l); hi = __uint_as_float(h);
}
__device__ __forceinline__ u64 fma2_(u64 a, u64 b, u64 c) {
    u64 d; asm("fma.rn.f32x2 %0, %1, %2, %3;" : "=l"(d) : "l"(a), "l"(b), "l"(c)); return d;
}
__device__ __forceinline__ u64 mul2_(u64 a, u64 b) {
    u64 d; asm("mul.rn.f32x2 %0, %1, %2;" : "=l"(d) : "l"(a), "l"(b)); return d;
}

// ---- mbarrier helpers ----
__device__ __forceinline__ void mbar_init(u32 addr, u32 count) {
    asm volatile("mbarrier.init.shared.b64 [%0], %1;" :: "r"(addr), "r"(count) : "memory");
}
__device__ __forceinline__ void mbar_arrive(u32 addr) {
    asm volatile("mbarrier.arrive.release.cta.shared::cta.b64 _, [%0];" :: "r"(addr) : "memory");
}
__device__ __forceinline__ void mbar_wait(u32 addr, u32 parity) {
    asm volatile(
        "{\n\t.reg .pred P;\n\t"
        "WL%=:\n\t"
        "mbarrier.try_wait.parity.acquire.cta.shared::cta.b64 P, [%0], %1, 0x989680;\n\t"
        "@P bra WD%=;\n\t"
        "bra WL%=;\n\t"
        "WD%=:\n\t}"
        :: "r"(addr), "r"(parity) : "memory");
}
__device__ __forceinline__ void cp16(u32 dst, const void* s) {
    asm volatile("cp.async.cg.shared.global [%0], [%1], 16;" :: "r"(dst), "l"(s));
}
__device__ __forceinline__ void cp4(u32 dst, const void* s) {
    asm volatile("cp.async.ca.shared.global [%0], [%1], 4;" :: "r"(dst), "l"(s));
}

// smem per-step stage (floats) — proven R4 layout:
// [0,32) kf | [32,64) qf | [64,192) ks swizzled: chunk g at 64+(g>>1)*4+(g&1)*64
// [192,320) qs same | [320,384) vf | [384,448) vs | [448,453) scalars | pad 456
#define STEP_F 456
#define MEGA   8                 // steps per mega-stage
#define NMEGA  3                 // ring = 24 steps = 43.8 KB static smem (< 48 KB)
#define NMEGAI (T_STEPS/MEGA)    // 256 mega-iterations

// per-step register staging (software pipeline, double-buffered)
struct SR {
    float4 sc4, vf4, vs4;
    float  msv;
    u64 kf, qf;
    ulonglong2 kA, kB, qA, qB;
};

__device__ __forceinline__ void loadregs(SR& r, const float* cur, int kgp, int cg) {
    r.sc4 = *(const float4*)(cur + 448);
    r.msv = cur[452];
    r.vf4 = *(const float4*)(cur + 320 + cg*4);
    r.vs4 = *(const float4*)(cur + 384 + cg*4);
    r.kf  = *(const u64*)(cur + 2*kgp);
    r.qf  = *(const u64*)(cur + 32 + 2*kgp);
    r.kA  = *(const ulonglong2*)(cur + 64  + kgp*4);
    r.kB  = *(const ulonglong2*)(cur + 128 + kgp*4);
    r.qA  = *(const ulonglong2*)(cur + 192 + kgp*4);
    r.qB  = *(const ulonglong2*)(cur + 256 + kgp*4);
}

__global__ __launch_bounds__(288, 1)
void e90_kernel(const float* __restrict__ k_fast, const float* __restrict__ v_fast,
                const float* __restrict__ q_fast, const float* __restrict__ decay_fast,
                const float* __restrict__ k_slow, const float* __restrict__ v_slow,
                const float* __restrict__ q_slow, const float* __restrict__ decay_slow,
                const float* __restrict__ slow_gate, const float* __restrict__ mix_fast,
                const float* __restrict__ mix_slow, const float* __restrict__ S_fast0,
                const float* __restrict__ S_slow0, float* __restrict__ out)
{
    __shared__ __align__(16) float ring[NMEGA * MEGA * STEP_F];
    __shared__ __align__(8)  u64  mbar[2 * NMEGA];   // [0..2] full, [3..5] empty

    const int tid = threadIdx.x;
    const int bh  = blockIdx.x;

    const u32 sb = (u32)__cvta_generic_to_shared(ring);
    const u32 bb = (u32)__cvta_generic_to_shared(mbar);

    if (tid == 0) {
        #pragma unroll
        for (int i = 0; i < NMEGA; i++) {
            mbar_init(bb + i*8, 32);                 // full: 32 producer-lane arrives
            mbar_init(bb + (NMEGA + i)*8, 8);        // empty: 8 consumer-warp arrives
        }
    }
    __syncthreads();   // the ONLY block barrier

    if (tid >= 256) {
        // ================= PRODUCER WARP =================
        const int lane = tid - 256;
        const float* src[4];
        int off[4], strd[4], wid[4];
        #pragma unroll
        for (int r = 0; r < 4; r++) {
            int c = r*32 + lane;
            src[r] = 0; off[r] = -1; strd[r] = 0; wid[r] = 1;
            if (c < 8)        {               src[r] = k_fast + (size_t)bh*KF + c*4;  off[r] = c*4;                        strd[r] = BH*KF; }
            else if (c < 16)  { int g = c-8;  src[r] = q_fast + (size_t)bh*KF + g*4;  off[r] = 32  + g*4;                  strd[r] = BH*KF; }
            else if (c < 48)  { int g = c-16; src[r] = k_slow + (size_t)bh*KS + g*4;  off[r] = 64  + (g>>1)*4 + (g&1)*64;  strd[r] = BH*KS; }
            else if (c < 80)  { int g = c-48; src[r] = q_slow + (size_t)bh*KS + g*4;  off[r] = 192 + (g>>1)*4 + (g&1)*64;  strd[r] = BH*KS; }
            else if (c < 96)  { int g = c-80; src[r] = v_fast + (size_t)bh*VF + g*4;  off[r] = 320 + g*4;                  strd[r] = BH*VF; }
            else if (c < 112) { int g = c-96; src[r] = v_slow + (size_t)bh*VS + g*4;  off[r] = 384 + g*4;                  strd[r] = BH*VS; }
            else if (c < 117) {
                const float* a5[5] = {decay_fast, decay_slow, slow_gate, mix_fast, mix_slow};
                src[r] = a5[c-112] + bh; off[r] = 448 + (c-112); strd[r] = BH; wid[r] = 0;
            }
        }

        int sm = 0; u32 eph = 1;   // fresh empty barriers pass parity-1 wait immediately
        for (int m = 0; m < NMEGAI; m++) {
            mbar_wait(bb + (NMEGA + sm)*8, eph);     // wait stage free
            u32 stg = sb + (u32)(sm * MEGA * STEP_F) * 4u;
            #pragma unroll
            for (int s = 0; s < MEGA; s++) {
                u32 stp = stg + (u32)(s * STEP_F) * 4u;
                #pragma unroll
                for (int r = 0; r < 4; r++) {
                    if (off[r] >= 0) {
                        u32 dst = stp + (u32)off[r] * 4u;
                        if (wid[r]) cp16(dst, src[r]); else cp4(dst, src[r]);
                        src[r] += strd[r];
                    }
                }
            }
            asm volatile("cp.async.mbarrier.arrive.noinc.shared.b64 [%0];" :: "r"(bb + sm*8) : "memory");
            if (sm == NMEGA-1) { sm = 0; eph ^= 1; } else sm++;
        }
    } else {
        // ================= 8 CONSUMER WARPS =================
        const int kgp = tid & 15;   // k-group (16 groups)
        const int cg  = tid >> 4;   // column-group (16 groups of 4 columns)

        u64 Sf[4], Ss[4][4];
        {
            const float* p0 = S_fast0 + (size_t)bh*KF*VF + (size_t)(2*kgp)*VF + cg*4;
            float4 re = *(const float4*)p0;
            float4 ro = *(const float4*)(p0 + VF);
            Sf[0] = pack2(re.x, ro.x); Sf[1] = pack2(re.y, ro.y);
            Sf[2] = pack2(re.z, ro.z); Sf[3] = pack2(re.w, ro.w);
            #pragma unroll
            for (int p = 0; p < 4; p++) {
                const float* p1 = S_slow0 + (size_t)bh*KS*VS + (size_t)(8*kgp + 2*p)*VS + cg*4;
                float4 se = *(const float4*)p1;
                float4 so = *(const float4*)(p1 + VS);
                Ss[p][0] = pack2(se.x, so.x); Ss[p][1] = pack2(se.y, so.y);
                Ss[p][2] = pack2(se.z, so.z); Ss[p][3] = pack2(se.w, so.w);
            }
        }

        float* outO = out + (size_t)BH*(KF*VF + KS*VS) + (size_t)bh*VF + cg*4;
        const bool writer = (kgp == 0);
        const bool elect  = ((tid & 31) == 0);

        auto compute = [&](const SR& r) {
            float df = r.sc4.x, ds = r.sc4.y, g = r.sc4.z, mf = r.sc4.w;
            float ms = r.msv;
            float de = 1.0f + g * (ds - 1.0f);      // g*ds + (1-g)

            u64 df2 = pack2(df, df);
            u64 de2 = pack2(de, de);

            u64 vf2[4] = { pack2(r.vf4.x, r.vf4.x), pack2(r.vf4.y, r.vf4.y),
                           pack2(r.vf4.z, r.vf4.z), pack2(r.vf4.w, r.vf4.w) };
            float w0 = g*r.vs4.x, w1 = g*r.vs4.y, w2 = g*r.vs4.z, w3 = g*r.vs4.w;
            u64 vs2[4] = { pack2(w0, w0), pack2(w1, w1), pack2(w2, w2), pack2(w3, w3) };

            u64 accf[4];
            #pragma unroll
            for (int j = 0; j < 4; j++) {
                Sf[j]   = fma2_(df2, Sf[j], mul2_(r.kf, vf2[j]));
                accf[j] = mul2_(r.qf, Sf[j]);
            }

            u64 kk[4] = { r.kA.x, r.kA.y, r.kB.x, r.kB.y };
            u64 qq[4] = { r.qA.x, r.qA.y, r.qB.x, r.qB.y };
            u64 accs[4];
            #pragma unroll
            for (int j = 0; j < 4; j++) {
                Ss[0][j] = fma2_(de2, Ss[0][j], mul2_(kk[0], vs2[j]));
                accs[j]  = mul2_(qq[0], Ss[0][j]);
            }
            #pragma unroll
            for (int p = 1; p < 4; p++) {
                #pragma unroll
                for (int j = 0; j < 4; j++) {
                    Ss[p][j] = fma2_(de2, Ss[p][j], mul2_(kk[p], vs2[j]));
                    accs[j]  = fma2_(qq[p], Ss[p][j], accs[j]);
                }
            }

            u64 mf2 = pack2(mf, mf), ms2 = pack2(ms, ms);
            float o[4];
            #pragma unroll
            for (int j = 0; j < 4; j++) {
                u64 mm = fma2_(ms2, accs[j], mul2_(mf2, accf[j]));
                float lo, hi; unpack2(mm, lo, hi);
                o[j] = lo + hi;
            }
            u64 o01 = pack2(o[0], o[1]);
            u64 o23 = pack2(o[2], o[3]);

            #pragma unroll
            for (int msk = 1; msk < 16; msk <<= 1) {
                u32 lo0, hi0, lo1, hi1;
                asm("mov.b64 {%0, %1}, %2;" : "=r"(lo0), "=r"(hi0) : "l"(o01));
                asm("mov.b64 {%0, %1}, %2;" : "=r"(lo1), "=r"(hi1) : "l"(o23));
                lo0 = __shfl_xor_sync(0xffffffffu, lo0, msk, 16);
                hi0 = __shfl_xor_sync(0xffffffffu, hi0, msk, 16);
                lo1 = __shfl_xor_sync(0xffffffffu, lo1, msk, 16);
                hi1 = __shfl_xor_sync(0xffffffffu, hi1, msk, 16);
                u64 p01, p23;
                asm("mov.b64 %0, {%1, %2};" : "=l"(p01) : "r"(lo0), "r"(hi0));
                asm("mov.b64 %0, {%1, %2};" : "=l"(p23) : "r"(lo1), "r"(hi1));
                asm("add.rn.f32x2 %0, %0, %1;" : "+l"(o01) : "l"(p01));
                asm("add.rn.f32x2 %0, %0, %1;" : "+l"(o23) : "l"(p23));
            }
            if (writer) {
                float a0, a1, a2, a3;
                unpack2(o01, a0, a1);
                unpack2(o23, a2, a3);
                *(float4*)outO = make_float4(a0, a1, a2, a3);
            }
            outO += (size_t)BH * VF;
        };

        SR R[2];
        int sm = 0; u32 cph = 0;
        mbar_wait(bb + 0, 0);
        loadregs(R[0], ring, kgp, cg);

        for (int m = 0; m < NMEGAI; m++) {
            const float* base = ring + sm * MEGA * STEP_F;
            #pragma unroll
            for (int s = 0; s < MEGA; s++) {
                if (s < MEGA-1)
                    loadregs(R[(s+1)&1], base + (s+1)*STEP_F, kgp, cg);
                compute(R[s&1]);
            }
            if (elect) mbar_arrive(bb + (NMEGA + sm)*8);   // stage consumed (reads done)
            int nsm = (sm == NMEGA-1) ? 0 : sm+1;
            u32 nc  = (sm == NMEGA-1) ? (cph ^ 1) : cph;
            if (m < NMEGAI-1) {
                mbar_wait(bb + nsm*8, nc);                 // next stage full (acquire)
                loadregs(R[0], ring + nsm * MEGA * STEP_F, kgp, cg);
            }
            sm = nsm; cph = nc;
        }

        // final states
        {
            float* oSf = out + (size_t)bh*KF*VF + (size_t)(2*kgp)*VF + cg*4;
            float e0,o0,e1,o1,e2,o2,e3,o3;
            unpack2(Sf[0], e0, o0); unpack2(Sf[1], e1, o1);
            unpack2(Sf[2], e2, o2); unpack2(Sf[3], e3, o3);
            *(float4*)oSf        = make_float4(e0, e1, e2, e3);
            *(float4*)(oSf + VF) = make_float4(o0, o1, o2, o3);

            #pragma unroll
            for (int p = 0; p < 4; p++) {
                float* oSs = out + (size_t)BH*KF*VF + (size_t)bh*KS*VS + (size_t)(8*kgp + 2*p)*VS + cg*4;
                float se0,so0,se1,so1,se2,so2,se3,so3;
                unpack2(Ss[p][0], se0, so0); unpack2(Ss[p][1], se1, so1);
                unpack2(Ss[p][2], se2, so2); unpack2(Ss[p][3], se3, so3);
                *(float4*)oSs        = make_float4(se0, se1, se2, se3);
                *(float4*)(oSs + VS) = make_float4(so0, so1, so2, so3);
            }
        }
    }
}

extern "C" void kernel_launch(void* const* d_in, const int* in_sizes, int n_in,
                              void* d_out, int out_size) {
    (void)in_sizes; (void)n_in; (void)out_size;
    e90_kernel<<<BH, 288>>>(
        (const float*)d_in[0],  (const float*)d_in[1],  (const float*)d_in[2],
        (const float*)d_in[3],  (const float*)d_in[4],  (const float*)d_in[5],
        (const float*)d_in[6],  (const float*)d_in[7],  (const float*)d_in[8],
        (const float*)d_in[9],  (const float*)d_in[10], (const float*)d_in[11],
        (const float*)d_in[12], (float*)d_out);
}